// round 7
// baseline (speedup 1.0000x reference)
#include <cuda_runtime.h>
#include <cuda_bf16.h>

#define N      512
#define DIM    256
#define EPSV   1e-12f
#define KLOG2E 14.426950408889634f   // SCAL(=10) * log2(e)

#define NBLK   128                   // 4 anchors per block, 1 block/SM

__device__ float    g_partial[NBLK];
__device__ float    g_pcount[NBLK];
__device__ unsigned g_done = 0;

__device__ __forceinline__ float ex2a(float x) {
    float y; asm("ex2.approx.ftz.f32 %0, %1;" : "=f"(y) : "f"(x)); return y;
}
__device__ __forceinline__ float rcpa(float x) {
    float y; asm("rcp.approx.ftz.f32 %0, %1;" : "=f"(y) : "f"(x)); return y;
}

// ---------------------------------------------------------------------------
// One kernel, 128 independent blocks x 512 threads.
// Block b owns anchors 4b..4b+3.
//   GEMM: A (4 rows) in smem as float4-per-k (broadcast reads);
//         B streamed global->registers (each thread exclusively owns 2 rows,
//         split over 2 k-halves: u = tid&255 -> rows {2u,2u+1}, kh = tid>>8).
//         No smem B tile, no barriers in the main loop.
//   Then: k-half combine via smem, D rows -> xsh, triplet sums, final reduce.
// ---------------------------------------------------------------------------
__global__ void __launch_bounds__(512)
k_all(const float* __restrict__ feat, const int* __restrict__ y,
      float* __restrict__ out) {
    __shared__ float4 As4[DIM];          // (a0,a1,a2,a3) per k   : 4 KB
    __shared__ float  sqa[4];
    __shared__ int    ysh[N];            // 2 KB
    __shared__ float  stage[256][10];    // k-half combine        : 10 KB
    __shared__ float  xsh[4][N];         // scaled D rows         : 8 KB
    __shared__ float  posR[4][132];
    __shared__ float  wsum[16];
    __shared__ float  red[NBLK];
    __shared__ int    npos_s[4], nneg_s[4], last_s;

    const int tid   = threadIdx.x;
    const int bid   = blockIdx.x;
    const int warp  = tid >> 5;
    const int lane  = tid & 31;
    const int abase = bid * 4;

    const float4* f4 = reinterpret_cast<const float4*>(feat);   // row pitch 64

    // ---- stage anchor rows, transposed to float4-per-k ----
    if (tid < 256) {
        const int q = tid >> 6, c = tid & 63;                    // row q, f4 col c
        const float4 v = __ldg(&f4[(abase + q) * 64 + c]);
        float* AsT = reinterpret_cast<float*>(As4);
        AsT[(4 * c + 0) * 4 + q] = v.x;
        AsT[(4 * c + 1) * 4 + q] = v.y;
        AsT[(4 * c + 2) * 4 + q] = v.z;
        AsT[(4 * c + 3) * 4 + q] = v.w;
    }
    ysh[tid] = y[tid];
    __syncthreads();

    if (warp < 4) {          // anchor squared norms
        const float* AsT = reinterpret_cast<const float*>(As4);
        float s = 0.f;
        #pragma unroll
        for (int k = lane; k < DIM; k += 32) {
            const float v = AsT[4 * k + warp];
            s += v * v;
        }
        #pragma unroll
        for (int o = 16; o > 0; o >>= 1) s += __shfl_xor_sync(0xffffffffu, s, o);
        if (lane == 0) sqa[warp] = s;
    }

    // ---- GEMM main loop: registers only, no barriers ----
    const int u  = tid & 255;
    const int kh = tid >> 8;
    const float4* pa = f4 + (2 * u)     * 64 + kh * 32;
    const float4* pb = f4 + (2 * u + 1) * 64 + kh * 32;

    float acc[4][2] = {};
    float sq0 = 0.f, sq1 = 0.f;

    #pragma unroll 4
    for (int t = 0; t < 32; ++t) {
        const float4 b0 = __ldg(pa + t);
        const float4 b1 = __ldg(pb + t);
        const float e0[4] = {b0.x, b0.y, b0.z, b0.w};
        const float e1[4] = {b1.x, b1.y, b1.z, b1.w};
        const int kbase = kh * 128 + 4 * t;
        #pragma unroll
        for (int r = 0; r < 4; ++r) {
            const float4 a = As4[kbase + r];
            acc[0][0] += a.x * e0[r]; acc[0][1] += a.x * e1[r];
            acc[1][0] += a.y * e0[r]; acc[1][1] += a.y * e1[r];
            acc[2][0] += a.z * e0[r]; acc[2][1] += a.z * e1[r];
            acc[3][0] += a.w * e0[r]; acc[3][1] += a.w * e1[r];
            sq0 += e0[r] * e0[r];
            sq1 += e1[r] * e1[r];
        }
    }

    // ---- combine k-halves, finalize scaled distances into xsh ----
    if (kh == 1) {
        #pragma unroll
        for (int q = 0; q < 4; ++q) {
            stage[u][2 * q]     = acc[q][0];
            stage[u][2 * q + 1] = acc[q][1];
        }
        stage[u][8] = sq0;
        stage[u][9] = sq1;
    }
    __syncthreads();
    if (kh == 0) {
        const float sj0 = sq0 + stage[u][8];
        const float sj1 = sq1 + stage[u][9];
        #pragma unroll
        for (int q = 0; q < 4; ++q) {
            const float d0 = acc[q][0] + stage[u][2 * q];
            const float d1 = acc[q][1] + stage[u][2 * q + 1];
            xsh[q][2 * u]     = sqrtf(fmaxf(sqa[q] + sj0 - 2.f * d0, EPSV)) * KLOG2E;
            xsh[q][2 * u + 1] = sqrtf(fmaxf(sqa[q] + sj1 - 2.f * d1, EPSV)) * KLOG2E;
        }
    }
    __syncthreads();

    // ---- positive lists: warp q handles anchor abase+q ----
    if (warp < 4) {
        const int   a  = abase + warp;
        const int   ya = ysh[a];
        const float c  = xsh[warp][(a + 1) & (N - 1)];
        int cnt = 0, same = 0;
        for (int base = 0; base < N; base += 32) {
            const int  j  = base + lane;
            const bool sc = (ysh[j] == ya);
            const bool v  = sc && (j != a);
            const unsigned mv = __ballot_sync(0xffffffffu, v);
            if (v) {
                const int slot = cnt + __popc(mv & ((1u << lane) - 1u));
                const float rp = ex2a(c - xsh[warp][j]);
                posR[warp][slot] = fminf(fmaxf(rp, 1e-30f), 1e30f);
            }
            cnt  += __popc(mv);
            same += __popc(__ballot_sync(0xffffffffu, sc));
        }
        if (lane == 0) { npos_s[warp] = cnt; nneg_s[warp] = N - same; }
    }
    __syncthreads();

    // ---- sigmoid sums: thread owns negative j = tid ----
    const float INF = __int_as_float(0x7f800000);
    const int   yn  = ysh[tid];

    float accT = 0.f;
    #pragma unroll
    for (int q = 0; q < 4; ++q) {
        const int   a  = abase + q;
        const int   ya = ysh[a];
        const float c  = xsh[q][(a + 1) & (N - 1)];
        const float e  = (yn != ya) ? ex2a(xsh[q][tid] - c) : INF;
        const int npos = npos_s[q];
        for (int p = 0; p < npos; ++p)
            accT += rcpa(fmaf(e, posR[q][p], 1.f));
    }

    #pragma unroll
    for (int o = 16; o > 0; o >>= 1) accT += __shfl_xor_sync(0xffffffffu, accT, o);
    if (lane == 0) wsum[warp] = accT;
    __syncthreads();

    if (tid == 0) {
        float s = 0.f;
        #pragma unroll
        for (int w = 0; w < 16; ++w) s += wsum[w];
        int cc = 0;
        #pragma unroll
        for (int q = 0; q < 4; ++q) cc += npos_s[q] * nneg_s[q];
        g_partial[bid] = s;
        g_pcount[bid]  = (float)cc;
        __threadfence();
        const unsigned t = atomicAdd(&g_done, 1u);
        last_s = (t == NBLK - 1);
    }
    __syncthreads();

    // ---- final reduce (last block) ----
    if (last_s) {
        __threadfence();
        if (tid < NBLK) red[tid] = __ldcg(&g_partial[tid]);
        __syncthreads();
        #pragma unroll
        for (int st = 64; st > 0; st >>= 1) {
            if (tid < st) red[tid] += red[tid + st];
            __syncthreads();
        }
        const float tot = red[0];
        __syncthreads();
        if (tid < NBLK) red[tid] = __ldcg(&g_pcount[tid]);
        __syncthreads();
        #pragma unroll
        for (int st = 64; st > 0; st >>= 1) {
            if (tid < st) red[tid] += red[tid + st];
            __syncthreads();
        }
        if (tid == 0) {
            out[0] = tot / red[0];
            g_done = 0;                  // reset for next graph replay
        }
    }
}

// ---------------------------------------------------------------------------
extern "C" void kernel_launch(void* const* d_in, const int* in_sizes, int n_in,
                              void* d_out, int out_size) {
    const float* feat = (const float*)d_in[0];
    // d_in[1] = logits (unused by the loss)
    const int*   y    = (const int*)d_in[2];
    float*       out  = (float*)d_out;

    k_all<<<NBLK, 512>>>(feat, y, out);
}

// round 8
// speedup vs baseline: 1.0537x; 1.0537x over previous
#include <cuda_runtime.h>
#include <cuda_bf16.h>

#define N      512
#define DIM    256
#define EPSV   1e-12f
#define KLOG2E 14.426950408889634f   // SCAL(=10) * log2(e)

#define NTRI   136                   // 16*17/2 triangular 32x32 tiles
#define TBLK   128                   // triplet blocks
#define APITCH 68                    // smem row pitch (floats), 272B = 17*16B
#define BPITCH 36                    // 144B = 9*16B

__device__ float    g_D[N * N];
__device__ float    g_partial[TBLK];
__device__ float    g_pcount[TBLK];
__device__ unsigned g_done = 0;

typedef unsigned long long ull;

__device__ __forceinline__ ull ffma2(ull a, ull b, ull c) {
    ull d; asm("fma.rn.f32x2 %0, %1, %2, %3;" : "=l"(d) : "l"(a), "l"(b), "l"(c));
    return d;
}
__device__ __forceinline__ ull addf2(ull a, ull b) {
    ull d; asm("add.rn.f32x2 %0, %1, %2;" : "=l"(d) : "l"(a), "l"(b));
    return d;
}
__device__ __forceinline__ void unpack2(ull v, float& lo, float& hi) {
    asm("mov.b64 {%0, %1}, %2;" : "=f"(lo), "=f"(hi) : "l"(v));
}
__device__ __forceinline__ float ex2a(float x) {
    float y; asm("ex2.approx.ftz.f32 %0, %1;" : "=f"(y) : "f"(x)); return y;
}
__device__ __forceinline__ float rcpa(float x) {
    float y; asm("rcp.approx.ftz.f32 %0, %1;" : "=f"(y) : "f"(x)); return y;
}

// ---------------------------------------------------------------------------
// Kernel 1: lower-triangle 32x32 distance tiles with f32x2 packed FMA.
// 136 blocks x 256 threads. Thread = (kh, jg, ig): microtile 2i x 4j over a
// 128-k half. A staged k-major duplicated (a,a); B staged k-major.
// Mirror-writes the transposed tile for ti != tj.
// ---------------------------------------------------------------------------
__global__ void __launch_bounds__(256)
k_dist(const float* __restrict__ feat) {
    __shared__ float Ad[2][32][APITCH];   // 17.4 KB, (a,a)-duplicated, k-major
    __shared__ float Bt[2][32][BPITCH];   // 9.2 KB, k-major
    __shared__ float sqi[32], sqj[32];
    __shared__ ull   stg[128][4];         // kh-half combine, 4 KB

    const int tid = threadIdx.x;
    int bid = blockIdx.x;

    // decode bid -> (ti, tj) with ti >= tj
    int ti = (int)((sqrtf(8.f * bid + 1.f) - 1.f) * 0.5f);
    if ((ti + 1) * (ti + 2) / 2 <= bid) ++ti;
    if (ti * (ti + 1) / 2 > bid) --ti;
    const int tj = bid - ti * (ti + 1) / 2;
    const int i0 = ti * 32, j0 = tj * 32;

    const float4* f4 = reinterpret_cast<const float4*>(feat);  // row pitch 64

    // ---- squared norms: 64 rows, 4 threads/row ----
    {
        const int r = tid >> 2, q = tid & 3;
        const int grow = (r < 32) ? (i0 + r) : (j0 + r - 32);
        float s = 0.f;
        #pragma unroll
        for (int u = 0; u < 16; ++u) {
            const float4 v = __ldg(&f4[grow * 64 + q * 16 + u]);
            s += v.x * v.x + v.y * v.y + v.z * v.z + v.w * v.w;
        }
        s += __shfl_xor_sync(0xffffffffu, s, 1);
        s += __shfl_xor_sync(0xffffffffu, s, 2);
        if (q == 0) { if (r < 32) sqi[r] = s; else sqj[r - 32] = s; }
    }

    const int kh = tid >> 7;       // k-half 0/1 (128 k each)
    const int r7 = tid & 127;
    const int ig = r7 & 15;        // i-group: rows 2ig, 2ig+1
    const int jg = r7 >> 4;        // j-group: cols 4jg..4jg+3

    ull acc00 = 0, acc01 = 0, acc10 = 0, acc11 = 0;

    // prefetch chunk 0
    float4 pfa[2], pfb[2];
    #pragma unroll
    for (int s = 0; s < 2; ++s) {
        const int v = tid + s * 256;
        const int khb = v >> 8, rem = v & 255, row = rem >> 3, kq = rem & 7;
        pfa[s] = __ldg(&f4[(i0 + row) * 64 + khb * 32 + kq]);
        pfb[s] = __ldg(&f4[(j0 + row) * 64 + khb * 32 + kq]);
    }

    for (int c = 0; c < 4; ++c) {         // 4 chunks of 32 k per half
        __syncthreads();
        #pragma unroll
        for (int s = 0; s < 2; ++s) {     // transpose-store staged chunk
            const int v = tid + s * 256;
            const int khb = v >> 8, rem = v & 255, row = rem >> 3, kq = rem & 7;
            const float av[4] = {pfa[s].x, pfa[s].y, pfa[s].z, pfa[s].w};
            const float bv[4] = {pfb[s].x, pfb[s].y, pfb[s].z, pfb[s].w};
            #pragma unroll
            for (int e = 0; e < 4; ++e) {
                Ad[khb][4 * kq + e][2 * row]     = av[e];
                Ad[khb][4 * kq + e][2 * row + 1] = av[e];
                Bt[khb][4 * kq + e][row]         = bv[e];
            }
        }
        __syncthreads();
        if (c < 3) {                      // prefetch next chunk (hides LDG)
            #pragma unroll
            for (int s = 0; s < 2; ++s) {
                const int v = tid + s * 256;
                const int khb = v >> 8, rem = v & 255, row = rem >> 3, kq = rem & 7;
                pfa[s] = __ldg(&f4[(i0 + row) * 64 + khb * 32 + (c + 1) * 8 + kq]);
                pfb[s] = __ldg(&f4[(j0 + row) * 64 + khb * 32 + (c + 1) * 8 + kq]);
            }
        }
        const float* Ab = &Ad[kh][0][4 * ig];
        const float* Bb = &Bt[kh][0][4 * jg];
        #pragma unroll
        for (int k = 0; k < 32; ++k) {
            const ulonglong2 a = *reinterpret_cast<const ulonglong2*>(Ab + k * APITCH);
            const ulonglong2 b = *reinterpret_cast<const ulonglong2*>(Bb + k * BPITCH);
            acc00 = ffma2(a.x, b.x, acc00);
            acc01 = ffma2(a.x, b.y, acc01);
            acc10 = ffma2(a.y, b.x, acc10);
            acc11 = ffma2(a.y, b.y, acc11);
        }
    }

    // ---- combine k-halves, finalize, write (+mirror) ----
    __syncthreads();
    if (kh == 1) {
        stg[r7][0] = acc00; stg[r7][1] = acc01;
        stg[r7][2] = acc10; stg[r7][3] = acc11;
    }
    __syncthreads();
    if (kh == 0) {
        acc00 = addf2(acc00, stg[r7][0]);
        acc01 = addf2(acc01, stg[r7][1]);
        acc10 = addf2(acc10, stg[r7][2]);
        acc11 = addf2(acc11, stg[r7][3]);
        float d[2][4];
        unpack2(acc00, d[0][0], d[0][1]); unpack2(acc01, d[0][2], d[0][3]);
        unpack2(acc10, d[1][0], d[1][1]); unpack2(acc11, d[1][2], d[1][3]);
        #pragma unroll
        for (int rr = 0; rr < 2; ++rr) {
            const int   row = 2 * ig + rr;
            const float si  = sqi[row];
            float o[4];
            #pragma unroll
            for (int cc = 0; cc < 4; ++cc)
                o[cc] = sqrtf(fmaxf(si + sqj[4 * jg + cc] - 2.f * d[rr][cc], EPSV));
            *reinterpret_cast<float4*>(&g_D[(i0 + row) * N + j0 + 4 * jg]) =
                make_float4(o[0], o[1], o[2], o[3]);
            if (ti != tj) {
                #pragma unroll
                for (int cc = 0; cc < 4; ++cc)
                    g_D[(j0 + 4 * jg + cc) * N + i0 + row] = o[cc];
            }
        }
    }
}

// ---------------------------------------------------------------------------
// Kernel 2: triplet sums. 128 blocks x 512 threads, 4 anchors/block (1 wave).
// sigmoid(K(Dp-Dn)) = 1/(1 + 2^{xn-c} * 2^{c-xp}); last block reduces.
// ---------------------------------------------------------------------------
__global__ void __launch_bounds__(512)
k_triplet(const int* __restrict__ y, float* __restrict__ out) {
    __shared__ float xsh[4][N];
    __shared__ int   ysh[N];
    __shared__ float posR[4][132];
    __shared__ float wsum[16];
    __shared__ float red[TBLK];
    __shared__ int   npos_s[4], nneg_s[4], last_s;

    const int tid   = threadIdx.x;
    const int bid   = blockIdx.x;
    const int warp  = tid >> 5;
    const int lane  = tid & 31;
    const int abase = bid * 4;

    ysh[tid] = y[tid];
    {
        const int q = tid >> 7, c4 = tid & 127;
        const float4* row4 = reinterpret_cast<const float4*>(&g_D[(abase + q) * N]);
        const float4 v = __ldcg(&row4[c4]);
        xsh[q][4 * c4 + 0] = v.x * KLOG2E;
        xsh[q][4 * c4 + 1] = v.y * KLOG2E;
        xsh[q][4 * c4 + 2] = v.z * KLOG2E;
        xsh[q][4 * c4 + 3] = v.w * KLOG2E;
    }
    __syncthreads();

    if (warp < 4) {                       // positive list for anchor abase+warp
        const int   a  = abase + warp;
        const int   ya = ysh[a];
        const float c  = xsh[warp][(a + 1) & (N - 1)];
        int cnt = 0, same = 0;
        for (int base = 0; base < N; base += 32) {
            const int  j  = base + lane;
            const bool sc = (ysh[j] == ya);
            const bool v  = sc && (j != a);
            const unsigned mv = __ballot_sync(0xffffffffu, v);
            if (v) {
                const int slot = cnt + __popc(mv & ((1u << lane) - 1u));
                const float rp = ex2a(c - xsh[warp][j]);
                posR[warp][slot] = fminf(fmaxf(rp, 1e-30f), 1e30f);
            }
            cnt  += __popc(mv);
            same += __popc(__ballot_sync(0xffffffffu, sc));
        }
        if (lane == 0) { npos_s[warp] = cnt; nneg_s[warp] = N - same; }
    }
    __syncthreads();

    const float INF = __int_as_float(0x7f800000);
    const int   yn  = ysh[tid];

    float accT = 0.f;
    #pragma unroll
    for (int q = 0; q < 4; ++q) {
        const int   a  = abase + q;
        const int   ya = ysh[a];
        const float c  = xsh[q][(a + 1) & (N - 1)];
        const float e  = (yn != ya) ? ex2a(xsh[q][tid] - c) : INF;
        const int npos = npos_s[q];
        for (int p = 0; p < npos; ++p)
            accT += rcpa(fmaf(e, posR[q][p], 1.f));
    }

    #pragma unroll
    for (int o = 16; o > 0; o >>= 1) accT += __shfl_xor_sync(0xffffffffu, accT, o);
    if (lane == 0) wsum[warp] = accT;
    __syncthreads();

    if (tid == 0) {
        float s = 0.f;
        #pragma unroll
        for (int w = 0; w < 16; ++w) s += wsum[w];
        int cc = 0;
        #pragma unroll
        for (int q = 0; q < 4; ++q) cc += npos_s[q] * nneg_s[q];
        g_partial[bid] = s;
        g_pcount[bid]  = (float)cc;
        __threadfence();
        const unsigned t = atomicAdd(&g_done, 1u);
        last_s = (t == TBLK - 1);
    }
    __syncthreads();

    if (last_s) {
        __threadfence();
        if (tid < TBLK) red[tid] = __ldcg(&g_partial[tid]);
        __syncthreads();
        #pragma unroll
        for (int st = 64; st > 0; st >>= 1) {
            if (tid < st) red[tid] += red[tid + st];
            __syncthreads();
        }
        const float tot = red[0];
        __syncthreads();
        if (tid < TBLK) red[tid] = __ldcg(&g_pcount[tid]);
        __syncthreads();
        #pragma unroll
        for (int st = 64; st > 0; st >>= 1) {
            if (tid < st) red[tid] += red[tid + st];
            __syncthreads();
        }
        if (tid == 0) {
            out[0] = tot / red[0];
            g_done = 0;                   // reset for next graph replay
        }
    }
}

// ---------------------------------------------------------------------------
extern "C" void kernel_launch(void* const* d_in, const int* in_sizes, int n_in,
                              void* d_out, int out_size) {
    const float* feat = (const float*)d_in[0];
    // d_in[1] = logits (unused by the loss)
    const int*   y    = (const int*)d_in[2];
    float*       out  = (float*)d_out;

    k_dist   <<<NTRI, 256>>>(feat);
    k_triplet<<<TBLK, 512>>>(y, out);
}

// round 9
// speedup vs baseline: 1.6305x; 1.5475x over previous
#include <cuda_runtime.h>
#include <cuda_bf16.h>

#define N      512
#define DIM    256
#define EPSV   1e-12f
#define KLOG2E 14.426950408889634f   // SCAL(=10) * log2(e)

#define NTRI   136                   // 16*17/2 triangular 32x32 tiles
#define TBLK   512                   // triplet blocks (1 anchor each)
#define APITCH 68                    // 272B = 17*16B
#define BPITCH 36                    // 144B = 9*16B

__device__ float    g_D[N * N];
__device__ float    g_partial[TBLK];
__device__ float    g_pcount[TBLK];
__device__ unsigned g_done = 0;

typedef unsigned long long ull;

__device__ __forceinline__ ull ffma2(ull a, ull b, ull c) {
    ull d; asm("fma.rn.f32x2 %0, %1, %2, %3;" : "=l"(d) : "l"(a), "l"(b), "l"(c));
    return d;
}
__device__ __forceinline__ ull addf2(ull a, ull b) {
    ull d; asm("add.rn.f32x2 %0, %1, %2;" : "=l"(d) : "l"(a), "l"(b));
    return d;
}
__device__ __forceinline__ void unpack2(ull v, float& lo, float& hi) {
    asm("mov.b64 {%0, %1}, %2;" : "=f"(lo), "=f"(hi) : "l"(v));
}
__device__ __forceinline__ float ex2a(float x) {
    float y; asm("ex2.approx.ftz.f32 %0, %1;" : "=f"(y) : "f"(x)); return y;
}
__device__ __forceinline__ float rcpa(float x) {
    float y; asm("rcp.approx.ftz.f32 %0, %1;" : "=f"(y) : "f"(x)); return y;
}

// ---------------------------------------------------------------------------
// Kernel 1: lower-triangle 32x32 distance tiles, f32x2 FMA, 512 threads.
// Thread = (kq in 0..3 [64-k quarter], jg, ig): 2i x 4j microtile.
// A staged k-major duplicated (a,a); B staged k-major. Mirror-write if ti!=tj.
// ---------------------------------------------------------------------------
__global__ void __launch_bounds__(512)
k_dist(const float* __restrict__ feat) {
    __shared__ __align__(16) float Ad[4][16][APITCH];   // 17.4 KB
    __shared__ __align__(16) float Bt[4][16][BPITCH];   //  9.2 KB
    __shared__ float sqi[32], sqj[32];
    __shared__ ull   stg[3][128][4];                    // 12 KB

    const int tid = threadIdx.x;
    const int bid = blockIdx.x;

    // decode bid -> (ti, tj), ti >= tj
    int ti = (int)((sqrtf(8.f * bid + 1.f) - 1.f) * 0.5f);
    if ((ti + 1) * (ti + 2) / 2 <= bid) ++ti;
    if (ti * (ti + 1) / 2 > bid) --ti;
    const int tj = bid - ti * (ti + 1) / 2;
    const int i0 = ti * 32, j0 = tj * 32;

    const float4* f4 = reinterpret_cast<const float4*>(feat);  // row pitch 64

    // ---- squared norms: 64 rows, 8 threads/row ----
    {
        const int r = tid >> 3, q = tid & 7;
        const int grow = (r < 32) ? (i0 + r) : (j0 + r - 32);
        float s = 0.f;
        #pragma unroll
        for (int u = 0; u < 8; ++u) {
            const float4 v = __ldg(&f4[grow * 64 + q * 8 + u]);
            s += v.x * v.x + v.y * v.y + v.z * v.z + v.w * v.w;
        }
        s += __shfl_xor_sync(0xffffffffu, s, 1);
        s += __shfl_xor_sync(0xffffffffu, s, 2);
        s += __shfl_xor_sync(0xffffffffu, s, 4);
        if (q == 0) { if (r < 32) sqi[r] = s; else sqj[r - 32] = s; }
    }

    const int kq = tid >> 7;       // k quarter 0..3 (64 k each)
    const int r7 = tid & 127;
    const int ig = r7 & 15;        // rows 2ig, 2ig+1
    const int jg = r7 >> 4;        // cols 4jg..4jg+3

    ull acc00 = 0, acc01 = 0, acc10 = 0, acc11 = 0;

    // staging mapping: quarter khb, row 0..31, f4 slot kf 0..3 (16 k / chunk)
    const int khb = tid >> 7;
    const int rem = tid & 127;
    const int row = rem >> 2;
    const int kf  = rem & 3;

    float4 pfa = __ldg(&f4[(i0 + row) * 64 + khb * 16 + kf]);
    float4 pfb = __ldg(&f4[(j0 + row) * 64 + khb * 16 + kf]);

    for (int c = 0; c < 4; ++c) {              // 4 chunks of 16 k per quarter
        __syncthreads();
        {
            const float av[4] = {pfa.x, pfa.y, pfa.z, pfa.w};
            const float bv[4] = {pfb.x, pfb.y, pfb.z, pfb.w};
            #pragma unroll
            for (int e = 0; e < 4; ++e) {
                Ad[khb][4 * kf + e][2 * row]     = av[e];
                Ad[khb][4 * kf + e][2 * row + 1] = av[e];
                Bt[khb][4 * kf + e][row]         = bv[e];
            }
        }
        __syncthreads();
        if (c < 3) {
            pfa = __ldg(&f4[(i0 + row) * 64 + khb * 16 + (c + 1) * 4 + kf]);
            pfb = __ldg(&f4[(j0 + row) * 64 + khb * 16 + (c + 1) * 4 + kf]);
        }
        const float* Ab = &Ad[kq][0][4 * ig];
        const float* Bb = &Bt[kq][0][4 * jg];
        #pragma unroll
        for (int k = 0; k < 16; ++k) {
            const ulonglong2 a = *reinterpret_cast<const ulonglong2*>(Ab + k * APITCH);
            const ulonglong2 b = *reinterpret_cast<const ulonglong2*>(Bb + k * BPITCH);
            acc00 = ffma2(a.x, b.x, acc00);
            acc01 = ffma2(a.x, b.y, acc01);
            acc10 = ffma2(a.y, b.x, acc10);
            acc11 = ffma2(a.y, b.y, acc11);
        }
    }

    // ---- combine the 4 k-quarters, finalize, write (+mirror) ----
    __syncthreads();
    if (kq >= 1) {
        stg[kq - 1][r7][0] = acc00; stg[kq - 1][r7][1] = acc01;
        stg[kq - 1][r7][2] = acc10; stg[kq - 1][r7][3] = acc11;
    }
    __syncthreads();
    if (kq == 0) {
        #pragma unroll
        for (int s = 0; s < 3; ++s) {
            acc00 = addf2(acc00, stg[s][r7][0]);
            acc01 = addf2(acc01, stg[s][r7][1]);
            acc10 = addf2(acc10, stg[s][r7][2]);
            acc11 = addf2(acc11, stg[s][r7][3]);
        }
        float d[2][4];
        unpack2(acc00, d[0][0], d[0][1]); unpack2(acc01, d[0][2], d[0][3]);
        unpack2(acc10, d[1][0], d[1][1]); unpack2(acc11, d[1][2], d[1][3]);
        #pragma unroll
        for (int rr = 0; rr < 2; ++rr) {
            const int   orow = 2 * ig + rr;
            const float si   = sqi[orow];
            float o[4];
            #pragma unroll
            for (int cc = 0; cc < 4; ++cc)
                o[cc] = sqrtf(fmaxf(si + sqj[4 * jg + cc] - 2.f * d[rr][cc], EPSV));
            *reinterpret_cast<float4*>(&g_D[(i0 + orow) * N + j0 + 4 * jg]) =
                make_float4(o[0], o[1], o[2], o[3]);
            if (ti != tj) {
                #pragma unroll
                for (int cc = 0; cc < 4; ++cc)
                    g_D[(j0 + 4 * jg + cc) * N + i0 + orow] = o[cc];
            }
        }
    }
}

// ---------------------------------------------------------------------------
// Kernel 2: triplet sums. 512 blocks x 256 threads, 1 anchor/block.
// posR padded to mult-of-4 with +INF (exact 0 contribution); float4 loads,
// 8 sigmoids in flight over 4 accumulators. Last block reduces.
// ---------------------------------------------------------------------------
__global__ void __launch_bounds__(256)
k_triplet(const int* __restrict__ y, float* __restrict__ out) {
    __shared__ float xsh[N];
    __shared__ int   ysh[N];
    __shared__ __align__(16) float posR[136];
    __shared__ float wsum[8];
    __shared__ float red[256];
    __shared__ int   npos_s, nneg_s, last_s;

    const int a    = blockIdx.x;
    const int tid  = threadIdx.x;
    const int warp = tid >> 5;
    const int lane = tid & 31;
    const float INF = __int_as_float(0x7f800000);

    {   // load + scale the anchor's D row (float2 per thread)
        const float2 v = __ldcg(&reinterpret_cast<const float2*>(&g_D[a * N])[tid]);
        xsh[2 * tid]     = v.x * KLOG2E;
        xsh[2 * tid + 1] = v.y * KLOG2E;
    }
    ysh[tid]       = y[tid];
    ysh[tid + 256] = y[tid + 256];
    __syncthreads();

    const int   ya = ysh[a];
    const float c  = xsh[(a + 1) & (N - 1)];

    if (warp == 0) {    // build positive list, pad with INF
        int cnt = 0, same = 0;
        for (int base = 0; base < N; base += 32) {
            const int  j  = base + lane;
            const bool sc = (ysh[j] == ya);
            const bool v  = sc && (j != a);
            const unsigned mv = __ballot_sync(0xffffffffu, v);
            if (v) {
                const int slot = cnt + __popc(mv & ((1u << lane) - 1u));
                const float rp = ex2a(c - xsh[j]);
                posR[slot] = fminf(fmaxf(rp, 1e-30f), 1e30f);
            }
            cnt  += __popc(mv);
            same += __popc(__ballot_sync(0xffffffffu, sc));
        }
        for (int s = cnt + lane; s < 136; s += 32) posR[s] = INF;
        if (lane == 0) { npos_s = cnt; nneg_s = N - same; }
    }
    __syncthreads();

    const float x0 = xsh[tid];
    const float x1 = xsh[tid + 256];
    float e0 = fmaxf(ex2a(x0 - c), 1e-30f);
    float e1 = fmaxf(ex2a(x1 - c), 1e-30f);
    if (ysh[tid]       == ya) e0 = INF;     // masked -> contributes exactly 0
    if (ysh[tid + 256] == ya) e1 = INF;

    const int np4 = (npos_s + 3) >> 2;
    const float4* pr4 = reinterpret_cast<const float4*>(posR);

    float acc0 = 0.f, acc1 = 0.f, acc2 = 0.f, acc3 = 0.f;
    for (int p4 = 0; p4 < np4; ++p4) {
        const float4 r = pr4[p4];
        acc0 += rcpa(fmaf(e0, r.x, 1.f));
        acc1 += rcpa(fmaf(e0, r.y, 1.f));
        acc2 += rcpa(fmaf(e0, r.z, 1.f));
        acc3 += rcpa(fmaf(e0, r.w, 1.f));
        acc0 += rcpa(fmaf(e1, r.x, 1.f));
        acc1 += rcpa(fmaf(e1, r.y, 1.f));
        acc2 += rcpa(fmaf(e1, r.z, 1.f));
        acc3 += rcpa(fmaf(e1, r.w, 1.f));
    }
    float accT = (acc0 + acc1) + (acc2 + acc3);

    #pragma unroll
    for (int o = 16; o > 0; o >>= 1) accT += __shfl_xor_sync(0xffffffffu, accT, o);
    if (lane == 0) wsum[warp] = accT;
    __syncthreads();

    if (tid == 0) {
        float s = 0.f;
        #pragma unroll
        for (int w = 0; w < 8; ++w) s += wsum[w];
        g_partial[a] = s;
        g_pcount[a]  = (float)(npos_s * nneg_s);
        __threadfence();
        const unsigned t = atomicAdd(&g_done, 1u);
        last_s = (t == TBLK - 1);
    }
    __syncthreads();

    if (last_s) {
        __threadfence();
        red[tid] = __ldcg(&g_partial[tid]) + __ldcg(&g_partial[tid + 256]);
        __syncthreads();
        #pragma unroll
        for (int st = 128; st > 0; st >>= 1) {
            if (tid < st) red[tid] += red[tid + st];
            __syncthreads();
        }
        const float tot = red[0];
        __syncthreads();
        red[tid] = __ldcg(&g_pcount[tid]) + __ldcg(&g_pcount[tid + 256]);
        __syncthreads();
        #pragma unroll
        for (int st = 128; st > 0; st >>= 1) {
            if (tid < st) red[tid] += red[tid + st];
            __syncthreads();
        }
        if (tid == 0) {
            out[0] = tot / red[0];
            g_done = 0;                   // reset for next graph replay
        }
    }
}

// ---------------------------------------------------------------------------
extern "C" void kernel_launch(void* const* d_in, const int* in_sizes, int n_in,
                              void* d_out, int out_size) {
    const float* feat = (const float*)d_in[0];
    // d_in[1] = logits (unused by the loss)
    const int*   y    = (const int*)d_in[2];
    float*       out  = (float*)d_out;

    k_dist   <<<NTRI, 512>>>(feat);
    k_triplet<<<TBLK, 256>>>(y, out);
}